// round 1
// baseline (speedup 1.0000x reference)
#include <cuda_runtime.h>
#include <cstdint>

#define S_TOK 8192
#define MDIM  2048
#define EEXP  8
#define HDIM  8192
#define CAP   2048

// ---------------- scratch (static device globals; no allocation) ----------
__device__ int   g_idx[S_TOK];            // expert id per token
__device__ float g_gw[S_TOK];             // gate weight per token (0 if dropped)
__device__ int   g_tfs[EEXP * CAP];       // token id for (expert, slot)
__device__ int   g_rows[EEXP];            // live rows per expert (<= CAP)
__device__ float g_h[(size_t)EEXP * CAP * HDIM];   // GEMM1 output (512 MB)

// ---------------- gate: logits -> argmax + softmax prob ------------------
__global__ void gate_kernel(const float* __restrict__ x, const float* __restrict__ Wg) {
    int s = blockIdx.x;
    int w = threadIdx.x >> 5, lane = threadIdx.x & 31;
    const float* xr = x + (size_t)s * MDIM;
    float sum = 0.f;
    for (int m = lane; m < MDIM; m += 32)
        sum += xr[m] * Wg[m * EEXP + w];
    #pragma unroll
    for (int o = 16; o; o >>= 1) sum += __shfl_xor_sync(0xffffffffu, sum, o);
    __shared__ float lg[EEXP];
    if (lane == 0) lg[w] = sum;
    __syncthreads();
    if (threadIdx.x == 0) {
        float mx = lg[0]; int mi = 0;
        #pragma unroll
        for (int e = 1; e < EEXP; e++) { if (lg[e] > mx) { mx = lg[e]; mi = e; } }
        float se = 0.f;
        #pragma unroll
        for (int e = 0; e < EEXP; e++) se += expf(lg[e] - mx);
        g_idx[s] = mi;
        g_gw[s]  = 1.f / se;   // = softmax prob of the argmax expert
    }
}

// ---------------- routing: order-dependent capacity assignment ------------
__global__ void route_kernel() {
    int lane = threadIdx.x;            // single warp
    int cnt = 0;                       // lane e (e<8) owns count for expert e
    for (int s0 = 0; s0 < S_TOK; s0 += 32) {
        int s  = s0 + lane;
        int id = g_idx[s];
        int pos = 0;
        #pragma unroll
        for (int e = 0; e < EEXP; e++) {
            unsigned b = __ballot_sync(0xffffffffu, id == e);
            int base   = __shfl_sync(0xffffffffu, cnt, e);
            if (id == e)   pos = base + __popc(b & ((1u << lane) - 1u));
            if (lane == e) cnt += __popc(b);
        }
        if (pos < CAP) g_tfs[id * CAP + pos] = s;
        else           g_gw[s] = 0.f;        // dropped
    }
    if (lane < EEXP) g_rows[lane] = min(cnt, CAP);
}

// ---------------- helpers --------------------------------------------------
__device__ __forceinline__ float gelu_tanh(float v) {
    float t = tanhf(0.7978845608028654f * (v + 0.044715f * v * v * v));
    return 0.5f * v * (1.f + t);
}
__device__ __forceinline__ unsigned long long dup2(float a) {
    unsigned au = __float_as_uint(a);
    unsigned long long r;
    asm("mov.b64 %0, {%1, %1};" : "=l"(r) : "r"(au));
    return r;
}
__device__ __forceinline__ void unpack2(unsigned long long p, float& lo, float& hi) {
    unsigned l, h;
    asm("mov.b64 {%0, %1}, %2;" : "=r"(l), "=r"(h) : "l"(p));
    lo = __uint_as_float(l); hi = __uint_as_float(h);
}
__device__ __forceinline__ void ffma2(unsigned long long& acc,
                                      unsigned long long a, unsigned long long b) {
    asm("fma.rn.f32x2 %0, %1, %2, %0;" : "+l"(acc) : "l"(a), "l"(b));
}

// ---------------- GEMM1: h = gelu(gather(x) @ W1[e]),  K = MDIM -----------
__global__ __launch_bounds__(256)
void gemm1_kernel(const float* __restrict__ x, const float* __restrict__ W1) {
    int e = blockIdx.z;
    int rows = g_rows[e];
    int rowBase = blockIdx.y * 128;
    if (rowBase >= rows) return;
    int colBase = blockIdx.x * 128;
    const float* B = W1 + (size_t)e * MDIM * HDIM;

    __shared__ float As[16][128];
    __shared__ float Bs[16][128];

    int tid = threadIdx.x;
    const float* aPtr[2]; bool aValid[2];
    #pragma unroll
    for (int i = 0; i < 2; i++) {
        int id = tid + i * 256;
        int r  = rowBase + (id >> 2);
        aValid[i] = (r < rows);
        int tok = aValid[i] ? g_tfs[e * CAP + r] : 0;
        aPtr[i] = x + (size_t)tok * MDIM + (id & 3) * 4;
    }
    const float* bPtr[2];
    #pragma unroll
    for (int i = 0; i < 2; i++) {
        int id = tid + i * 256;
        bPtr[i] = B + (size_t)(id >> 5) * HDIM + colBase + (id & 31) * 4;
    }

    int ty = tid >> 4, tx = tid & 15;
    unsigned long long acc[8][4];
    #pragma unroll
    for (int i = 0; i < 8; i++)
        #pragma unroll
        for (int j = 0; j < 4; j++) acc[i][j] = 0ull;

    float4 aReg[2], bReg[2];
    #pragma unroll
    for (int i = 0; i < 2; i++) {
        aReg[i] = aValid[i] ? *(const float4*)(aPtr[i]) : make_float4(0,0,0,0);
        bReg[i] = *(const float4*)(bPtr[i]);
    }

    const int NK = MDIM / 16;
    for (int kt = 0; kt < NK; kt++) {
        #pragma unroll
        for (int i = 0; i < 2; i++) {
            int id = tid + i * 256;
            int r = id >> 2, k4 = (id & 3) * 4;
            As[k4 + 0][r] = aReg[i].x;  As[k4 + 1][r] = aReg[i].y;
            As[k4 + 2][r] = aReg[i].z;  As[k4 + 3][r] = aReg[i].w;
            *(float4*)&Bs[id >> 5][(id & 31) * 4] = bReg[i];
        }
        __syncthreads();
        if (kt + 1 < NK) {
            #pragma unroll
            for (int i = 0; i < 2; i++) {
                aReg[i] = aValid[i] ? *(const float4*)(aPtr[i] + (kt + 1) * 16)
                                    : make_float4(0,0,0,0);
                bReg[i] = *(const float4*)(bPtr[i] + (size_t)(kt + 1) * 16 * HDIM);
            }
        }
        #pragma unroll
        for (int kk = 0; kk < 16; kk++) {
            float a8[8];
            *(float4*)&a8[0] = *(const float4*)&As[kk][ty * 8];
            *(float4*)&a8[4] = *(const float4*)&As[kk][ty * 8 + 4];
            unsigned long long bp[4];
            ulonglong2 t0 = *(const ulonglong2*)&Bs[kk][tx * 8];
            ulonglong2 t1 = *(const ulonglong2*)&Bs[kk][tx * 8 + 4];
            bp[0] = t0.x; bp[1] = t0.y; bp[2] = t1.x; bp[3] = t1.y;
            #pragma unroll
            for (int i = 0; i < 8; i++) {
                unsigned long long ap = dup2(a8[i]);
                #pragma unroll
                for (int j = 0; j < 4; j++) ffma2(acc[i][j], ap, bp[j]);
            }
        }
        __syncthreads();
    }
    #pragma unroll
    for (int i = 0; i < 8; i++) {
        int r = rowBase + ty * 8 + i;
        if (r < rows) {
            float v[8];
            #pragma unroll
            for (int j = 0; j < 4; j++) unpack2(acc[i][j], v[2*j], v[2*j+1]);
            #pragma unroll
            for (int j = 0; j < 8; j++) v[j] = gelu_tanh(v[j]);
            float* dst = &g_h[((size_t)e * CAP + r) * HDIM + colBase + tx * 8];
            *(float4*)dst       = *(float4*)&v[0];
            *(float4*)(dst + 4) = *(float4*)&v[4];
        }
    }
}

// ---------------- GEMM2: out[token] = (h @ W2[e]) * gate_w,  K = HDIM ------
__global__ __launch_bounds__(256)
void gemm2_kernel(const float* __restrict__ W2, float* __restrict__ out) {
    int e = blockIdx.z;
    int rows = g_rows[e];
    int rowBase = blockIdx.y * 128;
    if (rowBase >= rows) return;
    int colBase = blockIdx.x * 128;
    const float* A = g_h + (size_t)e * CAP * HDIM;
    const float* B = W2  + (size_t)e * HDIM * MDIM;

    __shared__ float As[16][128];
    __shared__ float Bs[16][128];

    int tid = threadIdx.x;
    const float* aPtr[2]; bool aValid[2];
    #pragma unroll
    for (int i = 0; i < 2; i++) {
        int id = tid + i * 256;
        int r  = rowBase + (id >> 2);
        aValid[i] = (r < rows);
        aPtr[i] = A + (size_t)(aValid[i] ? r : 0) * HDIM + (id & 3) * 4;
    }
    const float* bPtr[2];
    #pragma unroll
    for (int i = 0; i < 2; i++) {
        int id = tid + i * 256;
        bPtr[i] = B + (size_t)(id >> 5) * MDIM + colBase + (id & 31) * 4;
    }

    int ty = tid >> 4, tx = tid & 15;
    unsigned long long acc[8][4];
    #pragma unroll
    for (int i = 0; i < 8; i++)
        #pragma unroll
        for (int j = 0; j < 4; j++) acc[i][j] = 0ull;

    float4 aReg[2], bReg[2];
    #pragma unroll
    for (int i = 0; i < 2; i++) {
        aReg[i] = aValid[i] ? *(const float4*)(aPtr[i]) : make_float4(0,0,0,0);
        bReg[i] = *(const float4*)(bPtr[i]);
    }

    const int NK = HDIM / 16;
    for (int kt = 0; kt < NK; kt++) {
        #pragma unroll
        for (int i = 0; i < 2; i++) {
            int id = tid + i * 256;
            int r = id >> 2, k4 = (id & 3) * 4;
            As[k4 + 0][r] = aReg[i].x;  As[k4 + 1][r] = aReg[i].y;
            As[k4 + 2][r] = aReg[i].z;  As[k4 + 3][r] = aReg[i].w;
            *(float4*)&Bs[id >> 5][(id & 31) * 4] = bReg[i];
        }
        __syncthreads();
        if (kt + 1 < NK) {
            #pragma unroll
            for (int i = 0; i < 2; i++) {
                aReg[i] = aValid[i] ? *(const float4*)(aPtr[i] + (kt + 1) * 16)
                                    : make_float4(0,0,0,0);
                bReg[i] = *(const float4*)(bPtr[i] + (size_t)(kt + 1) * 16 * MDIM);
            }
        }
        #pragma unroll
        for (int kk = 0; kk < 16; kk++) {
            float a8[8];
            *(float4*)&a8[0] = *(const float4*)&As[kk][ty * 8];
            *(float4*)&a8[4] = *(const float4*)&As[kk][ty * 8 + 4];
            unsigned long long bp[4];
            ulonglong2 t0 = *(const ulonglong2*)&Bs[kk][tx * 8];
            ulonglong2 t1 = *(const ulonglong2*)&Bs[kk][tx * 8 + 4];
            bp[0] = t0.x; bp[1] = t0.y; bp[2] = t1.x; bp[3] = t1.y;
            #pragma unroll
            for (int i = 0; i < 8; i++) {
                unsigned long long ap = dup2(a8[i]);
                #pragma unroll
                for (int j = 0; j < 4; j++) ffma2(acc[i][j], ap, bp[j]);
            }
        }
        __syncthreads();
    }
    #pragma unroll
    for (int i = 0; i < 8; i++) {
        int r = rowBase + ty * 8 + i;
        if (r < rows) {
            int tok  = g_tfs[e * CAP + r];
            float gw = g_gw[tok];
            float v[8];
            #pragma unroll
            for (int j = 0; j < 4; j++) unpack2(acc[i][j], v[2*j], v[2*j+1]);
            #pragma unroll
            for (int j = 0; j < 8; j++) v[j] *= gw;
            float* dst = out + (size_t)tok * MDIM + colBase + tx * 8;
            *(float4*)dst       = *(float4*)&v[0];
            *(float4*)(dst + 4) = *(float4*)&v[4];
        }
    }
}

// ---------------- launch ---------------------------------------------------
extern "C" void kernel_launch(void* const* d_in, const int* in_sizes, int n_in,
                              void* d_out, int out_size) {
    const float* x  = (const float*)d_in[0];
    const float* Wg = (const float*)d_in[1];
    const float* W1 = (const float*)d_in[2];
    const float* W2 = (const float*)d_in[3];
    float* out = (float*)d_out;

    gate_kernel<<<S_TOK, 256>>>(x, Wg);
    route_kernel<<<1, 32>>>();
    cudaMemsetAsync(d_out, 0, (size_t)S_TOK * MDIM * sizeof(float));
    gemm1_kernel<<<dim3(HDIM / 128, CAP / 128, EEXP), 256>>>(x, W1);
    gemm2_kernel<<<dim3(MDIM / 128, CAP / 128, EEXP), 256>>>(W2, out);
}

// round 2
// speedup vs baseline: 1.0060x; 1.0060x over previous
#include <cuda_runtime.h>
#include <cstdint>

#define S_TOK 8192
#define MDIM  2048
#define EEXP  8
#define HDIM  8192
#define CAP   2048

// ---------------- scratch (static device globals; no allocation) ----------
__device__ int   g_idx[S_TOK];            // expert id per token
__device__ float g_gw[S_TOK];             // gate weight per token (0 if dropped)
__device__ int   g_tfs[EEXP * CAP];       // token id for (expert, slot)
__device__ int   g_rows[EEXP];            // live rows per expert (<= CAP)
__device__ float g_h[(size_t)EEXP * CAP * HDIM];   // GEMM1 output (512 MB)

// ---------------- gate: logits -> argmax + softmax prob ------------------
__global__ void gate_kernel(const float* __restrict__ x, const float* __restrict__ Wg) {
    int s = blockIdx.x;
    int w = threadIdx.x >> 5, lane = threadIdx.x & 31;
    const float* xr = x + (size_t)s * MDIM;
    float sum = 0.f;
    for (int m = lane; m < MDIM; m += 32)
        sum += xr[m] * Wg[m * EEXP + w];
    #pragma unroll
    for (int o = 16; o; o >>= 1) sum += __shfl_xor_sync(0xffffffffu, sum, o);
    __shared__ float lg[EEXP];
    if (lane == 0) lg[w] = sum;
    __syncthreads();
    if (threadIdx.x == 0) {
        float mx = lg[0]; int mi = 0;
        #pragma unroll
        for (int e = 1; e < EEXP; e++) { if (lg[e] > mx) { mx = lg[e]; mi = e; } }
        float se = 0.f;
        #pragma unroll
        for (int e = 0; e < EEXP; e++) se += expf(lg[e] - mx);
        g_idx[s] = mi;
        g_gw[s]  = 1.f / se;   // = softmax prob of the argmax expert
    }
}

// ---------------- routing: order-dependent capacity assignment ------------
__global__ void route_kernel() {
    int lane = threadIdx.x;            // single warp
    int cnt = 0;                       // lane e (e<8) owns count for expert e
    for (int s0 = 0; s0 < S_TOK; s0 += 32) {
        int s  = s0 + lane;
        int id = g_idx[s];
        int pos = 0;
        #pragma unroll
        for (int e = 0; e < EEXP; e++) {
            unsigned b = __ballot_sync(0xffffffffu, id == e);
            int base   = __shfl_sync(0xffffffffu, cnt, e);
            if (id == e)   pos = base + __popc(b & ((1u << lane) - 1u));
            if (lane == e) cnt += __popc(b);
        }
        if (pos < CAP) g_tfs[id * CAP + pos] = s;
        else           g_gw[s] = 0.f;        // dropped
    }
    if (lane < EEXP) g_rows[lane] = min(cnt, CAP);
}

// ---------------- helpers --------------------------------------------------
__device__ __forceinline__ float gelu_tanh(float v) {
    float t = tanhf(0.7978845608028654f * (v + 0.044715f * v * v * v));
    return 0.5f * v * (1.f + t);
}
__device__ __forceinline__ unsigned long long dup2(float a) {
    unsigned au = __float_as_uint(a);
    unsigned long long r;
    asm("mov.b64 %0, {%1, %1};" : "=l"(r) : "r"(au));
    return r;
}
__device__ __forceinline__ void unpack2(unsigned long long p, float& lo, float& hi) {
    unsigned l, h;
    asm("mov.b64 {%0, %1}, %2;" : "=r"(l), "=r"(h) : "l"(p));
    lo = __uint_as_float(l); hi = __uint_as_float(h);
}
__device__ __forceinline__ void ffma2(unsigned long long& acc,
                                      unsigned long long a, unsigned long long b) {
    asm("fma.rn.f32x2 %0, %1, %2, %0;" : "+l"(acc) : "l"(a), "l"(b));
}

// ---------------- GEMM1: h = gelu(gather(x) @ W1[e]),  K = MDIM -----------
__global__ __launch_bounds__(256)
void gemm1_kernel(const float* __restrict__ x, const float* __restrict__ W1) {
    int e = blockIdx.z;
    int rows = g_rows[e];
    int rowBase = blockIdx.y * 128;
    if (rowBase >= rows) return;
    int colBase = blockIdx.x * 128;
    const float* B = W1 + (size_t)e * MDIM * HDIM;

    __shared__ float As[16][128];
    __shared__ float Bs[16][128];

    int tid = threadIdx.x;
    const float* aPtr[2]; bool aValid[2];
    #pragma unroll
    for (int i = 0; i < 2; i++) {
        int id = tid + i * 256;
        int r  = rowBase + (id >> 2);
        aValid[i] = (r < rows);
        int tok = aValid[i] ? g_tfs[e * CAP + r] : 0;
        aPtr[i] = x + (size_t)tok * MDIM + (id & 3) * 4;
    }
    const float* bPtr[2];
    #pragma unroll
    for (int i = 0; i < 2; i++) {
        int id = tid + i * 256;
        bPtr[i] = B + (size_t)(id >> 5) * HDIM + colBase + (id & 31) * 4;
    }

    int ty = tid >> 4, tx = tid & 15;
    unsigned long long acc[8][4];
    #pragma unroll
    for (int i = 0; i < 8; i++)
        #pragma unroll
        for (int j = 0; j < 4; j++) acc[i][j] = 0ull;

    float4 aReg[2], bReg[2];
    #pragma unroll
    for (int i = 0; i < 2; i++) {
        aReg[i] = aValid[i] ? *(const float4*)(aPtr[i]) : make_float4(0,0,0,0);
        bReg[i] = *(const float4*)(bPtr[i]);
    }

    const int NK = MDIM / 16;
    for (int kt = 0; kt < NK; kt++) {
        #pragma unroll
        for (int i = 0; i < 2; i++) {
            int id = tid + i * 256;
            int r = id >> 2, k4 = (id & 3) * 4;
            As[k4 + 0][r] = aReg[i].x;  As[k4 + 1][r] = aReg[i].y;
            As[k4 + 2][r] = aReg[i].z;  As[k4 + 3][r] = aReg[i].w;
            *(float4*)&Bs[id >> 5][(id & 31) * 4] = bReg[i];
        }
        __syncthreads();
        if (kt + 1 < NK) {
            #pragma unroll
            for (int i = 0; i < 2; i++) {
                aReg[i] = aValid[i] ? *(const float4*)(aPtr[i] + (kt + 1) * 16)
                                    : make_float4(0,0,0,0);
                bReg[i] = *(const float4*)(bPtr[i] + (size_t)(kt + 1) * 16 * HDIM);
            }
        }
        #pragma unroll
        for (int kk = 0; kk < 16; kk++) {
            float a8[8];
            *(float4*)&a8[0] = *(const float4*)&As[kk][ty * 8];
            *(float4*)&a8[4] = *(const float4*)&As[kk][ty * 8 + 4];
            unsigned long long bp[4];
            ulonglong2 t0 = *(const ulonglong2*)&Bs[kk][tx * 8];
            ulonglong2 t1 = *(const ulonglong2*)&Bs[kk][tx * 8 + 4];
            bp[0] = t0.x; bp[1] = t0.y; bp[2] = t1.x; bp[3] = t1.y;
            #pragma unroll
            for (int i = 0; i < 8; i++) {
                unsigned long long ap = dup2(a8[i]);
                #pragma unroll
                for (int j = 0; j < 4; j++) ffma2(acc[i][j], ap, bp[j]);
            }
        }
        __syncthreads();
    }
    #pragma unroll
    for (int i = 0; i < 8; i++) {
        int r = rowBase + ty * 8 + i;
        if (r < rows) {
            float v[8];
            #pragma unroll
            for (int j = 0; j < 4; j++) unpack2(acc[i][j], v[2*j], v[2*j+1]);
            #pragma unroll
            for (int j = 0; j < 8; j++) v[j] = gelu_tanh(v[j]);
            float* dst = &g_h[((size_t)e * CAP + r) * HDIM + colBase + tx * 8];
            *(float4*)dst       = *(float4*)&v[0];
            *(float4*)(dst + 4) = *(float4*)&v[4];
        }
    }
}

// ---------------- GEMM2: out[token] = (h @ W2[e]) * gate_w,  K = HDIM ------
__global__ __launch_bounds__(256)
void gemm2_kernel(const float* __restrict__ W2, float* __restrict__ out) {
    int e = blockIdx.z;
    int rows = g_rows[e];
    int rowBase = blockIdx.y * 128;
    if (rowBase >= rows) return;
    int colBase = blockIdx.x * 128;
    const float* A = g_h + (size_t)e * CAP * HDIM;
    const float* B = W2  + (size_t)e * HDIM * MDIM;

    __shared__ float As[16][128];
    __shared__ float Bs[16][128];

    int tid = threadIdx.x;
    const float* aPtr[2]; bool aValid[2];
    #pragma unroll
    for (int i = 0; i < 2; i++) {
        int id = tid + i * 256;
        int r  = rowBase + (id >> 2);
        aValid[i] = (r < rows);
        aPtr[i] = A + (size_t)(aValid[i] ? r : 0) * HDIM + (id & 3) * 4;
    }
    const float* bPtr[2];
    #pragma unroll
    for (int i = 0; i < 2; i++) {
        int id = tid + i * 256;
        bPtr[i] = B + (size_t)(id >> 5) * MDIM + colBase + (id & 31) * 4;
    }

    int ty = tid >> 4, tx = tid & 15;
    unsigned long long acc[8][4];
    #pragma unroll
    for (int i = 0; i < 8; i++)
        #pragma unroll
        for (int j = 0; j < 4; j++) acc[i][j] = 0ull;

    float4 aReg[2], bReg[2];
    #pragma unroll
    for (int i = 0; i < 2; i++) {
        aReg[i] = aValid[i] ? *(const float4*)(aPtr[i]) : make_float4(0,0,0,0);
        bReg[i] = *(const float4*)(bPtr[i]);
    }

    const int NK = HDIM / 16;
    for (int kt = 0; kt < NK; kt++) {
        #pragma unroll
        for (int i = 0; i < 2; i++) {
            int id = tid + i * 256;
            int r = id >> 2, k4 = (id & 3) * 4;
            As[k4 + 0][r] = aReg[i].x;  As[k4 + 1][r] = aReg[i].y;
            As[k4 + 2][r] = aReg[i].z;  As[k4 + 3][r] = aReg[i].w;
            *(float4*)&Bs[id >> 5][(id & 31) * 4] = bReg[i];
        }
        __syncthreads();
        if (kt + 1 < NK) {
            #pragma unroll
            for (int i = 0; i < 2; i++) {
                aReg[i] = aValid[i] ? *(const float4*)(aPtr[i] + (kt + 1) * 16)
                                    : make_float4(0,0,0,0);
                bReg[i] = *(const float4*)(bPtr[i] + (size_t)(kt + 1) * 16 * MDIM);
            }
        }
        #pragma unroll
        for (int kk = 0; kk < 16; kk++) {
            float a8[8];
            *(float4*)&a8[0] = *(const float4*)&As[kk][ty * 8];
            *(float4*)&a8[4] = *(const float4*)&As[kk][ty * 8 + 4];
            unsigned long long bp[4];
            ulonglong2 t0 = *(const ulonglong2*)&Bs[kk][tx * 8];
            ulonglong2 t1 = *(const ulonglong2*)&Bs[kk][tx * 8 + 4];
            bp[0] = t0.x; bp[1] = t0.y; bp[2] = t1.x; bp[3] = t1.y;
            #pragma unroll
            for (int i = 0; i < 8; i++) {
                unsigned long long ap = dup2(a8[i]);
                #pragma unroll
                for (int j = 0; j < 4; j++) ffma2(acc[i][j], ap, bp[j]);
            }
        }
        __syncthreads();
    }
    #pragma unroll
    for (int i = 0; i < 8; i++) {
        int r = rowBase + ty * 8 + i;
        if (r < rows) {
            int tok  = g_tfs[e * CAP + r];
            float gw = g_gw[tok];
            float v[8];
            #pragma unroll
            for (int j = 0; j < 4; j++) unpack2(acc[i][j], v[2*j], v[2*j+1]);
            #pragma unroll
            for (int j = 0; j < 8; j++) v[j] *= gw;
            float* dst = out + (size_t)tok * MDIM + colBase + tx * 8;
            *(float4*)dst       = *(float4*)&v[0];
            *(float4*)(dst + 4) = *(float4*)&v[4];
        }
    }
}

// ---------------- launch ---------------------------------------------------
extern "C" void kernel_launch(void* const* d_in, const int* in_sizes, int n_in,
                              void* d_out, int out_size) {
    const float* x  = (const float*)d_in[0];
    const float* Wg = (const float*)d_in[1];
    const float* W1 = (const float*)d_in[2];
    const float* W2 = (const float*)d_in[3];
    float* out = (float*)d_out;

    gate_kernel<<<S_TOK, 256>>>(x, Wg);
    route_kernel<<<1, 32>>>();
    cudaMemsetAsync(d_out, 0, (size_t)S_TOK * MDIM * sizeof(float));
    gemm1_kernel<<<dim3(HDIM / 128, CAP / 128, EEXP), 256>>>(x, W1);
    gemm2_kernel<<<dim3(MDIM / 128, CAP / 128, EEXP), 256>>>(W2, out);
}

// round 4
// speedup vs baseline: 2.6528x; 2.6369x over previous
#include <cuda_runtime.h>
#include <cuda_bf16.h>
#include <cstdint>

#define S_TOK 8192
#define MDIM  2048
#define EEXP  8
#define HDIM  8192
#define CAP   2048

// ----------------- static device scratch -----------------------------------
__device__ int   g_idx[S_TOK];
__device__ float g_gw[S_TOK];
__device__ int   g_tfs[EEXP * CAP];
__device__ int   g_rows[EEXP];
__device__ __align__(128) __nv_bfloat16 g_x_hi[(size_t)S_TOK * MDIM];
__device__ __align__(128) __nv_bfloat16 g_x_lo[(size_t)S_TOK * MDIM];
__device__ __align__(128) __nv_bfloat16 g_h_hi[(size_t)EEXP * CAP * HDIM];
__device__ __align__(128) __nv_bfloat16 g_h_lo[(size_t)EEXP * CAP * HDIM];
__device__ __align__(128) __nv_bfloat16 g_w1t_hi[(size_t)EEXP * HDIM * MDIM];
__device__ __align__(128) __nv_bfloat16 g_w1t_lo[(size_t)EEXP * HDIM * MDIM];
__device__ __align__(128) __nv_bfloat16 g_w2t_hi[(size_t)EEXP * MDIM * HDIM];
__device__ __align__(128) __nv_bfloat16 g_w2t_lo[(size_t)EEXP * MDIM * HDIM];

// ----------------- small helpers -------------------------------------------
__device__ __forceinline__ uint32_t smem_u32(const void* p) {
    uint32_t a;
    asm("{ .reg .u64 t; cvta.to.shared.u64 t, %1; cvt.u32.u64 %0, t; }" : "=r"(a) : "l"(p));
    return a;
}
__device__ __forceinline__ uint32_t SWZ(uint32_t o) { return o ^ ((o >> 3) & 0x70u); }

// pack two fp32 into bf16x2 hi and bf16x2 lo (elem0 -> low half)
__device__ __forceinline__ void cvt2(float f0, float f1, uint32_t& hi, uint32_t& lo) {
    asm("cvt.rn.bf16x2.f32 %0, %1, %2;" : "=r"(hi) : "f"(f1), "f"(f0));
    float h0 = __uint_as_float(hi << 16);
    float h1 = __uint_as_float(hi & 0xffff0000u);
    asm("cvt.rn.bf16x2.f32 %0, %1, %2;" : "=r"(lo) : "f"(f1 - h1), "f"(f0 - h0));
}
__device__ __forceinline__ void cpa(uint32_t d, const void* s) {
    asm volatile("cp.async.cg.shared.global [%0], [%1], 16;" :: "r"(d), "l"(s) : "memory");
}
__device__ __forceinline__ void ldsm4(uint32_t* r, uint32_t a) {
    asm volatile("ldmatrix.sync.aligned.m8n8.x4.shared.b16 {%0,%1,%2,%3}, [%4];"
                 : "=r"(r[0]), "=r"(r[1]), "=r"(r[2]), "=r"(r[3]) : "r"(a));
}
__device__ __forceinline__ void mmabf(float* c, const uint32_t* a, uint32_t b0, uint32_t b1) {
    asm volatile("mma.sync.aligned.m16n8k16.row.col.f32.bf16.bf16.f32 "
                 "{%0,%1,%2,%3}, {%4,%5,%6,%7}, {%8,%9}, {%0,%1,%2,%3};"
                 : "+f"(c[0]), "+f"(c[1]), "+f"(c[2]), "+f"(c[3])
                 : "r"(a[0]), "r"(a[1]), "r"(a[2]), "r"(a[3]), "r"(b0), "r"(b1));
}
__device__ __forceinline__ float gelu_tanh(float v) {
    float t = tanhf(0.7978845608028654f * (v + 0.044715f * v * v * v));
    return 0.5f * v * (1.f + t);
}

// ----------------- gate ----------------------------------------------------
__global__ void gate_kernel(const float* __restrict__ x, const float* __restrict__ Wg) {
    int s = blockIdx.x;
    int w = threadIdx.x >> 5, lane = threadIdx.x & 31;
    const float* xr = x + (size_t)s * MDIM;
    float sum = 0.f;
    for (int m = lane; m < MDIM; m += 32)
        sum += xr[m] * Wg[m * EEXP + w];
    #pragma unroll
    for (int o = 16; o; o >>= 1) sum += __shfl_xor_sync(0xffffffffu, sum, o);
    __shared__ float lg[EEXP];
    if (lane == 0) lg[w] = sum;
    __syncthreads();
    if (threadIdx.x == 0) {
        float mx = lg[0]; int mi = 0;
        #pragma unroll
        for (int e = 1; e < EEXP; e++) if (lg[e] > mx) { mx = lg[e]; mi = e; }
        float se = 0.f;
        #pragma unroll
        for (int e = 0; e < EEXP; e++) se += expf(lg[e] - mx);
        g_idx[s] = mi;
        g_gw[s]  = 1.f / se;
    }
}

// ----------------- routing -------------------------------------------------
__global__ void route_kernel() {
    int lane = threadIdx.x;
    int cnt = 0;
    for (int s0 = 0; s0 < S_TOK; s0 += 32) {
        int s  = s0 + lane;
        int id = g_idx[s];
        int pos = 0;
        #pragma unroll
        for (int e = 0; e < EEXP; e++) {
            unsigned b = __ballot_sync(0xffffffffu, id == e);
            int base   = __shfl_sync(0xffffffffu, cnt, e);
            if (id == e)   pos = base + __popc(b & ((1u << lane) - 1u));
            if (lane == e) cnt += __popc(b);
        }
        if (pos < CAP) g_tfs[id * CAP + pos] = s;
        else           g_gw[s] = 0.f;
    }
    if (lane < EEXP) g_rows[lane] = min(cnt, CAP);
}

// ----------------- x split to bf16 hi/lo -----------------------------------
__global__ void split_x(const float4* __restrict__ x) {
    size_t i = (size_t)blockIdx.x * 256 + threadIdx.x;   // S*M/4 total
    float4 v = x[i];
    uint32_t h0, l0, h1, l1;
    cvt2(v.x, v.y, h0, l0);
    cvt2(v.z, v.w, h1, l1);
    ((uint2*)g_x_hi)[i] = make_uint2(h0, h1);
    ((uint2*)g_x_lo)[i] = make_uint2(l0, l1);
}

// ----------------- weight transpose + split --------------------------------
template<bool W1SEL>
__global__ void transpose_split(const float* __restrict__ src) {
    constexpr int R  = W1SEL ? MDIM : HDIM;   // src rows (= out cols = K)
    constexpr int Cc = W1SEL ? HDIM : MDIM;   // src cols (= out rows = N)
    __nv_bfloat16* dhi = W1SEL ? g_w1t_hi : g_w2t_hi;
    __nv_bfloat16* dlo = W1SEL ? g_w1t_lo : g_w2t_lo;
    __shared__ float t[32][33];
    int e = blockIdx.z;
    const float* s = src + (size_t)e * R * Cc;
    size_t ob = (size_t)e * R * Cc;
    int c0 = blockIdx.x * 32, r0 = blockIdx.y * 32;
    int tx = threadIdx.x, ty = threadIdx.y;
    #pragma unroll
    for (int k = 0; k < 4; k++)
        t[ty + 8 * k][tx] = s[(size_t)(r0 + ty + 8 * k) * Cc + c0 + tx];
    __syncthreads();
    #pragma unroll
    for (int k = 0; k < 4; k++) {
        float v = t[tx][ty + 8 * k];
        int orow = c0 + ty + 8 * k, ocol = r0 + tx;
        __nv_bfloat16 h = __float2bfloat16(v);
        __nv_bfloat16 l = __float2bfloat16(v - __bfloat162float(h));
        dhi[ob + (size_t)orow * R + ocol] = h;
        dlo[ob + (size_t)orow * R + ocol] = l;
    }
}

// ----------------- HMMA split-bf16 GEMM ------------------------------------
#define BM 128
#define BN 256
#define BK 64
#define STG 98304
#define OFF_AHI 0
#define OFF_ALO 16384
#define OFF_BHI 32768
#define OFF_BLO 65536
#define SMEM_BYTES (2 * STG + 1024)

template<bool G1>
__global__ __launch_bounds__(256)
void hgemm(float* __restrict__ outp) {
    constexpr int KD  = G1 ? MDIM : HDIM;
    constexpr int NT  = G1 ? HDIM : MDIM;
    constexpr int KCH = KD / BK;

    int e = blockIdx.z;
    int rows = g_rows[e];
    int rowBase = blockIdx.y * BM;
    if (rowBase >= rows) return;
    int colBase = blockIdx.x * BN;

    extern __shared__ char dsm[];
    uint32_t base = (smem_u32(dsm) + 1023u) & ~1023u;

    int t = threadIdx.x;

    // ---- loader setup: thread t loads 64B halves of row (t>>1) ----
    int lr = t >> 1, half = t & 1;
    const __nv_bfloat16 *aHi, *aLo;
    if (G1) {
        int rr = rowBase + lr;
        if (rr >= rows) rr = rows - 1;
        int tok = g_tfs[e * CAP + rr];
        size_t o = (size_t)tok * MDIM + half * 32;
        aHi = g_x_hi + o;  aLo = g_x_lo + o;
    } else {
        size_t o = ((size_t)e * CAP + rowBase + lr) * HDIM + half * 32;
        aHi = g_h_hi + o;  aLo = g_h_lo + o;
    }
    size_t bo0 = ((size_t)e * NT + colBase + lr) * KD + half * 32;
    size_t bo1 = bo0 + (size_t)128 * KD;
    const __nv_bfloat16* bHi = G1 ? g_w1t_hi : g_w2t_hi;
    const __nv_bfloat16* bLo = G1 ? g_w1t_lo : g_w2t_lo;

    uint32_t d0[4], d1[4];
    #pragma unroll
    for (int i = 0; i < 4; i++) {
        d0[i] = SWZ(lr * 128 + (half * 4 + i) * 16);
        d1[i] = SWZ((lr + 128) * 128 + (half * 4 + i) * 16);
    }

    auto loadStage = [&](int s, int kt) {
        uint32_t sb = base + s * STG;
        int ko = kt * BK;
        #pragma unroll
        for (int i = 0; i < 4; i++) {
            cpa(sb + OFF_AHI + d0[i], aHi + ko + i * 8);
            cpa(sb + OFF_ALO + d0[i], aLo + ko + i * 8);
            cpa(sb + OFF_BHI + d0[i], bHi + bo0 + ko + i * 8);
            cpa(sb + OFF_BLO + d0[i], bLo + bo0 + ko + i * 8);
            cpa(sb + OFF_BHI + d1[i], bHi + bo1 + ko + i * 8);
            cpa(sb + OFF_BLO + d1[i], bLo + bo1 + ko + i * 8);
        }
    };

    // ---- compute setup ----
    int wid = t >> 5, lane = t & 31;
    int m0 = (wid >> 1) * 32, n0 = (wid & 1) * 128;
    uint32_t aOff[2];
    #pragma unroll
    for (int mt = 0; mt < 2; mt++)
        aOff[mt] = (m0 + mt * 16 + (lane & 15)) * 128 + ((lane >> 4) * 16);
    uint32_t bOff = (n0 + (lane & 7) + ((lane >> 4) << 3)) * 128 + (((lane >> 3) & 1) * 16);

    float acc[128];
    #pragma unroll
    for (int i = 0; i < 128; i++) acc[i] = 0.f;

    loadStage(0, 0); asm volatile("cp.async.commit_group;" ::: "memory");
    loadStage(1, 1); asm volatile("cp.async.commit_group;" ::: "memory");

    for (int kt = 0; kt < KCH; kt++) {
        asm volatile("cp.async.wait_group 1;" ::: "memory");
        __syncthreads();
        int s = kt & 1;
        uint32_t sb = base + s * STG;
        #pragma unroll
        for (int ks = 0; ks < 4; ks++) {
            uint32_t ah[2][4], al[2][4];
            #pragma unroll
            for (int mt = 0; mt < 2; mt++) {
                ldsm4(ah[mt], sb + OFF_AHI + SWZ(aOff[mt] + ks * 32));
                ldsm4(al[mt], sb + OFF_ALO + SWZ(aOff[mt] + ks * 32));
            }
            #pragma unroll
            for (int p = 0; p < 8; p++) {
                uint32_t bh[4], bl[4];
                ldsm4(bh, sb + OFF_BHI + SWZ(bOff + p * 2048 + ks * 32));
                ldsm4(bl, sb + OFF_BLO + SWZ(bOff + p * 2048 + ks * 32));
                #pragma unroll
                for (int mt = 0; mt < 2; mt++) {
                    float* c0 = &acc[(mt * 16 + 2 * p) * 4];
                    float* c1 = &acc[(mt * 16 + 2 * p + 1) * 4];
                    mmabf(c0, ah[mt], bh[0], bh[1]);   // hi*hi
                    mmabf(c1, ah[mt], bh[2], bh[3]);
                    mmabf(c0, ah[mt], bl[0], bl[1]);   // hi*lo
                    mmabf(c1, ah[mt], bl[2], bl[3]);
                    mmabf(c0, al[mt], bh[0], bh[1]);   // lo*hi
                    mmabf(c1, al[mt], bh[2], bh[3]);
                }
            }
        }
        __syncthreads();
        if (kt + 2 < KCH) loadStage(s, kt + 2);
        asm volatile("cp.async.commit_group;" ::: "memory");
    }

    // ---- epilogue ----
    int rq = lane >> 2, cq = (lane & 3) * 2;
    #pragma unroll
    for (int mt = 0; mt < 2; mt++) {
        #pragma unroll
        for (int h = 0; h < 2; h++) {
            int r = rowBase + m0 + mt * 16 + rq + h * 8;
            if (r < rows) {
                if (G1) {
                    size_t ro = ((size_t)e * CAP + r) * HDIM + colBase + n0 + cq;
                    #pragma unroll
                    for (int nt = 0; nt < 16; nt++) {
                        float v0 = gelu_tanh(acc[(mt * 16 + nt) * 4 + h * 2]);
                        float v1 = gelu_tanh(acc[(mt * 16 + nt) * 4 + h * 2 + 1]);
                        uint32_t hi, lo;
                        cvt2(v0, v1, hi, lo);
                        *(uint32_t*)(g_h_hi + ro + nt * 8) = hi;
                        *(uint32_t*)(g_h_lo + ro + nt * 8) = lo;
                    }
                } else {
                    int tok = g_tfs[e * CAP + r];
                    float gw = g_gw[tok];
                    float* dst = outp + (size_t)tok * MDIM + colBase + n0 + cq;
                    #pragma unroll
                    for (int nt = 0; nt < 16; nt++) {
                        float2 v;
                        v.x = acc[(mt * 16 + nt) * 4 + h * 2]     * gw;
                        v.y = acc[(mt * 16 + nt) * 4 + h * 2 + 1] * gw;
                        *(float2*)(dst + nt * 8) = v;
                    }
                }
            }
        }
    }
}

// ----------------- launch ---------------------------------------------------
extern "C" void kernel_launch(void* const* d_in, const int* in_sizes, int n_in,
                              void* d_out, int out_size) {
    const float* x  = (const float*)d_in[0];
    const float* Wg = (const float*)d_in[1];
    const float* W1 = (const float*)d_in[2];
    const float* W2 = (const float*)d_in[3];
    float* out = (float*)d_out;

    cudaFuncSetAttribute(hgemm<true>,  cudaFuncAttributeMaxDynamicSharedMemorySize, SMEM_BYTES);
    cudaFuncSetAttribute(hgemm<false>, cudaFuncAttributeMaxDynamicSharedMemorySize, SMEM_BYTES);

    gate_kernel<<<S_TOK, 256>>>(x, Wg);
    route_kernel<<<1, 32>>>();
    split_x<<<(S_TOK * MDIM / 4) / 256, 256>>>((const float4*)x);
    transpose_split<true ><<<dim3(HDIM / 32, MDIM / 32, EEXP), dim3(32, 8)>>>(W1);
    transpose_split<false><<<dim3(MDIM / 32, HDIM / 32, EEXP), dim3(32, 8)>>>(W2);
    cudaMemsetAsync(d_out, 0, (size_t)S_TOK * MDIM * sizeof(float));
    hgemm<true ><<<dim3(HDIM / BN, CAP / BM, EEXP), 256, SMEM_BYTES>>>(nullptr);
    hgemm<false><<<dim3(MDIM / BN, CAP / BM, EEXP), 256, SMEM_BYTES>>>(out);
}

// round 5
// speedup vs baseline: 3.6871x; 1.3899x over previous
#include <cuda_runtime.h>
#include <cuda_fp16.h>
#include <cstdint>

#define S_TOK 8192
#define MDIM  2048
#define EEXP  8
#define HDIM  8192
#define CAP   2048

// ----------------- static device scratch -----------------------------------
__device__ int   g_idx[S_TOK];
__device__ float g_gw[S_TOK];
__device__ int   g_tfs[EEXP * CAP];
__device__ int   g_rows[EEXP];
__device__ __align__(128) __half g_x_hi[(size_t)S_TOK * MDIM];
__device__ __align__(128) __half g_x_lo[(size_t)S_TOK * MDIM];
__device__ __align__(128) __half g_h_hi[(size_t)EEXP * CAP * HDIM];
__device__ __align__(128) __half g_h_lo[(size_t)EEXP * CAP * HDIM];
__device__ __align__(128) __half g_w1t_hi[(size_t)EEXP * HDIM * MDIM];
__device__ __align__(128) __half g_w2t_hi[(size_t)EEXP * MDIM * HDIM];

// ----------------- small helpers -------------------------------------------
__device__ __forceinline__ uint32_t smem_u32(const void* p) {
    uint32_t a;
    asm("{ .reg .u64 t; cvta.to.shared.u64 t, %1; cvt.u32.u64 %0, t; }" : "=r"(a) : "l"(p));
    return a;
}
__device__ __forceinline__ uint32_t SWZ(uint32_t o) { return o ^ ((o >> 3) & 0x70u); }

// pack two fp32 into f16x2 hi and f16x2 lo (elem0 -> low half)
__device__ __forceinline__ void cvt2h(float f0, float f1, uint32_t& hi, uint32_t& lo) {
    asm("cvt.rn.f16x2.f32 %0, %1, %2;" : "=r"(hi) : "f"(f1), "f"(f0));
    __half2 hv = *reinterpret_cast<__half2*>(&hi);
    float h0 = __low2float(hv), h1 = __high2float(hv);
    asm("cvt.rn.f16x2.f32 %0, %1, %2;" : "=r"(lo) : "f"(f1 - h1), "f"(f0 - h0));
}
__device__ __forceinline__ void cpa(uint32_t d, const void* s) {
    asm volatile("cp.async.cg.shared.global [%0], [%1], 16;" :: "r"(d), "l"(s) : "memory");
}
__device__ __forceinline__ void ldsm4(uint32_t* r, uint32_t a) {
    asm volatile("ldmatrix.sync.aligned.m8n8.x4.shared.b16 {%0,%1,%2,%3}, [%4];"
                 : "=r"(r[0]), "=r"(r[1]), "=r"(r[2]), "=r"(r[3]) : "r"(a));
}
__device__ __forceinline__ void mmah(float* c, const uint32_t* a, uint32_t b0, uint32_t b1) {
    asm volatile("mma.sync.aligned.m16n8k16.row.col.f32.f16.f16.f32 "
                 "{%0,%1,%2,%3}, {%4,%5,%6,%7}, {%8,%9}, {%0,%1,%2,%3};"
                 : "+f"(c[0]), "+f"(c[1]), "+f"(c[2]), "+f"(c[3])
                 : "r"(a[0]), "r"(a[1]), "r"(a[2]), "r"(a[3]), "r"(b0), "r"(b1));
}
__device__ __forceinline__ float gelu_tanh(float v) {
    float t = tanhf(0.7978845608028654f * (v + 0.044715f * v * v * v));
    return 0.5f * v * (1.f + t);
}

// ----------------- gate ----------------------------------------------------
__global__ void gate_kernel(const float* __restrict__ x, const float* __restrict__ Wg) {
    int s = blockIdx.x;
    int w = threadIdx.x >> 5, lane = threadIdx.x & 31;
    const float* xr = x + (size_t)s * MDIM;
    float sum = 0.f;
    for (int m = lane; m < MDIM; m += 32)
        sum += xr[m] * Wg[m * EEXP + w];
    #pragma unroll
    for (int o = 16; o; o >>= 1) sum += __shfl_xor_sync(0xffffffffu, sum, o);
    __shared__ float lg[EEXP];
    if (lane == 0) lg[w] = sum;
    __syncthreads();
    if (threadIdx.x == 0) {
        float mx = lg[0]; int mi = 0;
        #pragma unroll
        for (int e = 1; e < EEXP; e++) if (lg[e] > mx) { mx = lg[e]; mi = e; }
        float se = 0.f;
        #pragma unroll
        for (int e = 0; e < EEXP; e++) se += expf(lg[e] - mx);
        g_idx[s] = mi;
        g_gw[s]  = 1.f / se;
    }
}

// ----------------- routing -------------------------------------------------
__global__ void route_kernel() {
    int lane = threadIdx.x;
    int cnt = 0;
    for (int s0 = 0; s0 < S_TOK; s0 += 32) {
        int s  = s0 + lane;
        int id = g_idx[s];
        int pos = 0;
        #pragma unroll
        for (int e = 0; e < EEXP; e++) {
            unsigned b = __ballot_sync(0xffffffffu, id == e);
            int base   = __shfl_sync(0xffffffffu, cnt, e);
            if (id == e)   pos = base + __popc(b & ((1u << lane) - 1u));
            if (lane == e) cnt += __popc(b);
        }
        if (pos < CAP) g_tfs[id * CAP + pos] = s;
        else           g_gw[s] = 0.f;
    }
    if (lane < EEXP) g_rows[lane] = min(cnt, CAP);
}

// ----------------- x split to fp16 hi/lo -------------------------------------
__global__ void split_x(const float4* __restrict__ x) {
    size_t i = (size_t)blockIdx.x * 256 + threadIdx.x;   // S*M/4 total
    float4 v = x[i];
    uint32_t h0, l0, h1, l1;
    cvt2h(v.x, v.y, h0, l0);
    cvt2h(v.z, v.w, h1, l1);
    ((uint2*)g_x_hi)[i] = make_uint2(h0, h1);
    ((uint2*)g_x_lo)[i] = make_uint2(l0, l1);
}

// ----------------- weight transpose (hi only) -------------------------------
template<bool W1SEL>
__global__ void transpose_split(const float* __restrict__ src) {
    constexpr int R  = W1SEL ? MDIM : HDIM;   // src rows (= out cols = K)
    constexpr int Cc = W1SEL ? HDIM : MDIM;   // src cols (= out rows = N)
    __half* dhi = W1SEL ? g_w1t_hi : g_w2t_hi;
    __shared__ float t[32][33];
    int e = blockIdx.z;
    const float* s = src + (size_t)e * R * Cc;
    size_t ob = (size_t)e * R * Cc;
    int c0 = blockIdx.x * 32, r0 = blockIdx.y * 32;
    int tx = threadIdx.x, ty = threadIdx.y;
    #pragma unroll
    for (int k = 0; k < 4; k++)
        t[ty + 8 * k][tx] = s[(size_t)(r0 + ty + 8 * k) * Cc + c0 + tx];
    __syncthreads();
    #pragma unroll
    for (int k = 0; k < 4; k++) {
        float v = t[tx][ty + 8 * k];
        int orow = c0 + ty + 8 * k, ocol = r0 + tx;
        dhi[ob + (size_t)orow * R + ocol] = __float2half_rn(v);
    }
}

// ----------------- HMMA split-fp16 GEMM (2 passes) ---------------------------
#define BM 128
#define BN 256
#define BK 64
#define OFF_AHI 0
#define OFF_ALO 16384
#define OFF_BHI 32768
#define STG 65536
#define SMEM_BYTES (2 * STG + 1024)

template<bool G1>
__global__ __launch_bounds__(256)
void hgemm(float* __restrict__ outp) {
    constexpr int KD  = G1 ? MDIM : HDIM;
    constexpr int NT  = G1 ? HDIM : MDIM;
    constexpr int KCH = KD / BK;

    int e = blockIdx.z;
    int rows = g_rows[e];
    int rowBase = blockIdx.y * BM;
    if (rowBase >= rows) return;
    int colBase = blockIdx.x * BN;

    extern __shared__ char dsm[];
    uint32_t base = (smem_u32(dsm) + 1023u) & ~1023u;

    int t = threadIdx.x;

    // ---- loader setup: thread t loads 64B halves of row (t>>1) ----
    int lr = t >> 1, half = t & 1;
    const __half *aHi, *aLo;
    if (G1) {
        int rr = rowBase + lr;
        if (rr >= rows) rr = rows - 1;
        int tok = g_tfs[e * CAP + rr];
        size_t o = (size_t)tok * MDIM + half * 32;
        aHi = g_x_hi + o;  aLo = g_x_lo + o;
    } else {
        size_t o = ((size_t)e * CAP + rowBase + lr) * HDIM + half * 32;
        aHi = g_h_hi + o;  aLo = g_h_lo + o;
    }
    size_t bo0 = ((size_t)e * NT + colBase + lr) * KD + half * 32;
    size_t bo1 = bo0 + (size_t)128 * KD;
    const __half* bHi = G1 ? g_w1t_hi : g_w2t_hi;

    uint32_t d0[4], d1[4];
    #pragma unroll
    for (int i = 0; i < 4; i++) {
        d0[i] = SWZ(lr * 128 + (half * 4 + i) * 16);
        d1[i] = SWZ((lr + 128) * 128 + (half * 4 + i) * 16);
    }

    auto loadStage = [&](int s, int kt) {
        uint32_t sb = base + s * STG;
        int ko = kt * BK;
        #pragma unroll
        for (int i = 0; i < 4; i++) {
            cpa(sb + OFF_AHI + d0[i], aHi + ko + i * 8);
            cpa(sb + OFF_ALO + d0[i], aLo + ko + i * 8);
            cpa(sb + OFF_BHI + d0[i], bHi + bo0 + ko + i * 8);
            cpa(sb + OFF_BHI + d1[i], bHi + bo1 + ko + i * 8);
        }
    };

    // ---- compute setup ----
    int wid = t >> 5, lane = t & 31;
    int m0 = (wid >> 1) * 32, n0 = (wid & 1) * 128;
    uint32_t aOff[2];
    #pragma unroll
    for (int mt = 0; mt < 2; mt++)
        aOff[mt] = (m0 + mt * 16 + (lane & 15)) * 128 + ((lane >> 4) * 16);
    uint32_t bOff = (n0 + (lane & 7) + ((lane >> 4) << 3)) * 128 + (((lane >> 3) & 1) * 16);

    float acc[128];
    #pragma unroll
    for (int i = 0; i < 128; i++) acc[i] = 0.f;

    loadStage(0, 0); asm volatile("cp.async.commit_group;" ::: "memory");
    loadStage(1, 1); asm volatile("cp.async.commit_group;" ::: "memory");

    for (int kt = 0; kt < KCH; kt++) {
        asm volatile("cp.async.wait_group 1;" ::: "memory");
        __syncthreads();
        int s = kt & 1;
        uint32_t sb = base + s * STG;
        #pragma unroll
        for (int ks = 0; ks < 4; ks++) {
            uint32_t ah[2][4], al[2][4];
            #pragma unroll
            for (int mt = 0; mt < 2; mt++) {
                ldsm4(ah[mt], sb + OFF_AHI + SWZ(aOff[mt] + ks * 32));
                ldsm4(al[mt], sb + OFF_ALO + SWZ(aOff[mt] + ks * 32));
            }
            #pragma unroll
            for (int p = 0; p < 8; p++) {
                uint32_t bh[4];
                ldsm4(bh, sb + OFF_BHI + SWZ(bOff + p * 2048 + ks * 32));
                #pragma unroll
                for (int mt = 0; mt < 2; mt++) {
                    float* c0 = &acc[(mt * 16 + 2 * p) * 4];
                    float* c1 = &acc[(mt * 16 + 2 * p + 1) * 4];
                    mmah(c0, ah[mt], bh[0], bh[1]);   // hi*hi
                    mmah(c1, ah[mt], bh[2], bh[3]);
                    mmah(c0, al[mt], bh[0], bh[1]);   // lo*hi
                    mmah(c1, al[mt], bh[2], bh[3]);
                }
            }
        }
        __syncthreads();
        if (kt + 2 < KCH) loadStage(s, kt + 2);
        asm volatile("cp.async.commit_group;" ::: "memory");
    }

    // ---- epilogue ----
    int rq = lane >> 2, cq = (lane & 3) * 2;
    #pragma unroll
    for (int mt = 0; mt < 2; mt++) {
        #pragma unroll
        for (int h = 0; h < 2; h++) {
            int r = rowBase + m0 + mt * 16 + rq + h * 8;
            if (r < rows) {
                if (G1) {
                    size_t ro = ((size_t)e * CAP + r) * HDIM + colBase + n0 + cq;
                    #pragma unroll
                    for (int nt = 0; nt < 16; nt++) {
                        float v0 = gelu_tanh(acc[(mt * 16 + nt) * 4 + h * 2]);
                        float v1 = gelu_tanh(acc[(mt * 16 + nt) * 4 + h * 2 + 1]);
                        uint32_t hi, lo;
                        cvt2h(v0, v1, hi, lo);
                        *(uint32_t*)(g_h_hi + ro + nt * 8) = hi;
                        *(uint32_t*)(g_h_lo + ro + nt * 8) = lo;
                    }
                } else {
                    int tok = g_tfs[e * CAP + r];
                    float gw = g_gw[tok];
                    float* dst = outp + (size_t)tok * MDIM + colBase + n0 + cq;
                    #pragma unroll
                    for (int nt = 0; nt < 16; nt++) {
                        float2 v;
                        v.x = acc[(mt * 16 + nt) * 4 + h * 2]     * gw;
                        v.y = acc[(mt * 16 + nt) * 4 + h * 2 + 1] * gw;
                        *(float2*)(dst + nt * 8) = v;
                    }
                }
            }
        }
    }
}

// ----------------- launch ---------------------------------------------------
extern "C" void kernel_launch(void* const* d_in, const int* in_sizes, int n_in,
                              void* d_out, int out_size) {
    const float* x  = (const float*)d_in[0];
    const float* Wg = (const float*)d_in[1];
    const float* W1 = (const float*)d_in[2];
    const float* W2 = (const float*)d_in[3];
    float* out = (float*)d_out;

    cudaFuncSetAttribute(hgemm<true>,  cudaFuncAttributeMaxDynamicSharedMemorySize, SMEM_BYTES);
    cudaFuncSetAttribute(hgemm<false>, cudaFuncAttributeMaxDynamicSharedMemorySize, SMEM_BYTES);

    gate_kernel<<<S_TOK, 256>>>(x, Wg);
    route_kernel<<<1, 32>>>();
    split_x<<<(S_TOK * MDIM / 4) / 256, 256>>>((const float4*)x);
    transpose_split<true ><<<dim3(HDIM / 32, MDIM / 32, EEXP), dim3(32, 8)>>>(W1);
    transpose_split<false><<<dim3(MDIM / 32, HDIM / 32, EEXP), dim3(32, 8)>>>(W2);
    cudaMemsetAsync(d_out, 0, (size_t)S_TOK * MDIM * sizeof(float));
    hgemm<true ><<<dim3(HDIM / BN, CAP / BM, EEXP), 256, SMEM_BYTES>>>(nullptr);
    hgemm<false><<<dim3(MDIM / BN, CAP / BM, EEXP), 256, SMEM_BYTES>>>(out);
}

// round 6
// speedup vs baseline: 5.5865x; 1.5151x over previous
#include <cuda_runtime.h>
#include <cuda_fp16.h>
#include <cstdint>

#define S_TOK 8192
#define MDIM  2048
#define EEXP  8
#define HDIM  8192
#define CAP   2048

// ----------------- static device scratch -----------------------------------
__device__ int   g_idx[S_TOK];
__device__ float g_gw[S_TOK];
__device__ int   g_tfs[EEXP * CAP];
__device__ int   g_rows[EEXP];
__device__ __align__(128) __half g_x_hi[(size_t)S_TOK * MDIM];
__device__ __align__(128) __half g_h_hi[(size_t)EEXP * CAP * HDIM];
__device__ __align__(128) __half g_w1t_hi[(size_t)EEXP * HDIM * MDIM];
__device__ __align__(128) __half g_w2t_hi[(size_t)EEXP * MDIM * HDIM];

// ----------------- small helpers -------------------------------------------
__device__ __forceinline__ uint32_t smem_u32(const void* p) {
    uint32_t a;
    asm("{ .reg .u64 t; cvta.to.shared.u64 t, %1; cvt.u32.u64 %0, t; }" : "=r"(a) : "l"(p));
    return a;
}
__device__ __forceinline__ uint32_t SWZ(uint32_t o) { return o ^ ((o >> 3) & 0x70u); }

__device__ __forceinline__ uint32_t packh(float f0, float f1) {
    uint32_t r;
    asm("cvt.rn.f16x2.f32 %0, %1, %2;" : "=r"(r) : "f"(f1), "f"(f0));
    return r;
}
__device__ __forceinline__ void cpa(uint32_t d, const void* s) {
    asm volatile("cp.async.cg.shared.global [%0], [%1], 16;" :: "r"(d), "l"(s) : "memory");
}
__device__ __forceinline__ void ldsm4(uint32_t* r, uint32_t a) {
    asm volatile("ldmatrix.sync.aligned.m8n8.x4.shared.b16 {%0,%1,%2,%3}, [%4];"
                 : "=r"(r[0]), "=r"(r[1]), "=r"(r[2]), "=r"(r[3]) : "r"(a));
}
__device__ __forceinline__ void mmah(float* c, const uint32_t* a, uint32_t b0, uint32_t b1) {
    asm volatile("mma.sync.aligned.m16n8k16.row.col.f32.f16.f16.f32 "
                 "{%0,%1,%2,%3}, {%4,%5,%6,%7}, {%8,%9}, {%0,%1,%2,%3};"
                 : "+f"(c[0]), "+f"(c[1]), "+f"(c[2]), "+f"(c[3])
                 : "r"(a[0]), "r"(a[1]), "r"(a[2]), "r"(a[3]), "r"(b0), "r"(b1));
}
__device__ __forceinline__ float gelu_tanh(float v) {
    float t = tanhf(0.7978845608028654f * (v + 0.044715f * v * v * v));
    return 0.5f * v * (1.f + t);
}

// ----------------- gate ----------------------------------------------------
__global__ void gate_kernel(const float* __restrict__ x, const float* __restrict__ Wg) {
    int s = blockIdx.x;
    int w = threadIdx.x >> 5, lane = threadIdx.x & 31;
    const float* xr = x + (size_t)s * MDIM;
    float sum = 0.f;
    for (int m = lane; m < MDIM; m += 32)
        sum += xr[m] * Wg[m * EEXP + w];
    #pragma unroll
    for (int o = 16; o; o >>= 1) sum += __shfl_xor_sync(0xffffffffu, sum, o);
    __shared__ float lg[EEXP];
    if (lane == 0) lg[w] = sum;
    __syncthreads();
    if (threadIdx.x == 0) {
        float mx = lg[0]; int mi = 0;
        #pragma unroll
        for (int e = 1; e < EEXP; e++) if (lg[e] > mx) { mx = lg[e]; mi = e; }
        float se = 0.f;
        #pragma unroll
        for (int e = 0; e < EEXP; e++) se += expf(lg[e] - mx);
        g_idx[s] = mi;
        g_gw[s]  = 1.f / se;
    }
}

// ----------------- routing -------------------------------------------------
__global__ void route_kernel() {
    int lane = threadIdx.x;
    int cnt = 0;
    for (int s0 = 0; s0 < S_TOK; s0 += 32) {
        int s  = s0 + lane;
        int id = g_idx[s];
        int pos = 0;
        #pragma unroll
        for (int e = 0; e < EEXP; e++) {
            unsigned b = __ballot_sync(0xffffffffu, id == e);
            int base   = __shfl_sync(0xffffffffu, cnt, e);
            if (id == e)   pos = base + __popc(b & ((1u << lane) - 1u));
            if (lane == e) cnt += __popc(b);
        }
        if (pos < CAP) g_tfs[id * CAP + pos] = s;
        else           g_gw[s] = 0.f;
    }
    if (lane < EEXP) g_rows[lane] = min(cnt, CAP);
}

// ----------------- x convert to fp16 ----------------------------------------
__global__ void split_x(const float4* __restrict__ x) {
    size_t i = (size_t)blockIdx.x * 256 + threadIdx.x;   // S*M/4 total
    float4 v = x[i];
    ((uint2*)g_x_hi)[i] = make_uint2(packh(v.x, v.y), packh(v.z, v.w));
}

// ----------------- weight transpose (fp16) ----------------------------------
template<bool W1SEL>
__global__ void transpose_split(const float* __restrict__ src) {
    constexpr int R  = W1SEL ? MDIM : HDIM;   // src rows (= out cols = K)
    constexpr int Cc = W1SEL ? HDIM : MDIM;   // src cols (= out rows = N)
    __half* dhi = W1SEL ? g_w1t_hi : g_w2t_hi;
    __shared__ float t[32][33];
    int e = blockIdx.z;
    const float* s = src + (size_t)e * R * Cc;
    size_t ob = (size_t)e * R * Cc;
    int c0 = blockIdx.x * 32, r0 = blockIdx.y * 32;
    int tx = threadIdx.x, ty = threadIdx.y;
    #pragma unroll
    for (int k = 0; k < 4; k++)
        t[ty + 8 * k][tx] = s[(size_t)(r0 + ty + 8 * k) * Cc + c0 + tx];
    __syncthreads();
    #pragma unroll
    for (int k = 0; k < 4; k++) {
        float v = t[tx][ty + 8 * k];
        int orow = c0 + ty + 8 * k, ocol = r0 + tx;
        dhi[ob + (size_t)orow * R + ocol] = __float2half_rn(v);
    }
}

// ----------------- HMMA fp16 GEMM (single pass) ------------------------------
#define BM 128
#define BN 256
#define BK 64
#define OFF_AHI 0
#define OFF_BHI 16384
#define STG 49152
#define SMEM_BYTES (2 * STG + 1024)

template<bool G1>
__global__ __launch_bounds__(256)
void hgemm(float* __restrict__ outp) {
    constexpr int KD  = G1 ? MDIM : HDIM;
    constexpr int NT  = G1 ? HDIM : MDIM;
    constexpr int KCH = KD / BK;

    int e = blockIdx.z;
    int rows = g_rows[e];
    int rowBase = blockIdx.y * BM;
    if (rowBase >= rows) return;
    int colBase = blockIdx.x * BN;

    extern __shared__ char dsm[];
    uint32_t base = (smem_u32(dsm) + 1023u) & ~1023u;

    int t = threadIdx.x;

    // ---- loader setup: thread t loads 64B halves of row (t>>1) ----
    int lr = t >> 1, half = t & 1;
    const __half* aHi;
    if (G1) {
        int rr = rowBase + lr;
        if (rr >= rows) rr = rows - 1;
        int tok = g_tfs[e * CAP + rr];
        aHi = g_x_hi + (size_t)tok * MDIM + half * 32;
    } else {
        aHi = g_h_hi + ((size_t)e * CAP + rowBase + lr) * HDIM + half * 32;
    }
    size_t bo0 = ((size_t)e * NT + colBase + lr) * KD + half * 32;
    size_t bo1 = bo0 + (size_t)128 * KD;
    const __half* bHi = G1 ? g_w1t_hi : g_w2t_hi;

    uint32_t d0[4], d1[4];
    #pragma unroll
    for (int i = 0; i < 4; i++) {
        d0[i] = SWZ(lr * 128 + (half * 4 + i) * 16);
        d1[i] = SWZ((lr + 128) * 128 + (half * 4 + i) * 16);
    }

    auto loadStage = [&](int s, int kt) {
        uint32_t sb = base + s * STG;
        int ko = kt * BK;
        #pragma unroll
        for (int i = 0; i < 4; i++) {
            cpa(sb + OFF_AHI + d0[i], aHi + ko + i * 8);
            cpa(sb + OFF_BHI + d0[i], bHi + bo0 + ko + i * 8);
            cpa(sb + OFF_BHI + d1[i], bHi + bo1 + ko + i * 8);
        }
    };

    // ---- compute setup ----
    int wid = t >> 5, lane = t & 31;
    int m0 = (wid >> 1) * 32, n0 = (wid & 1) * 128;
    uint32_t aOff[2];
    #pragma unroll
    for (int mt = 0; mt < 2; mt++)
        aOff[mt] = (m0 + mt * 16 + (lane & 15)) * 128 + ((lane >> 4) * 16);
    uint32_t bOff = (n0 + (lane & 7) + ((lane >> 4) << 3)) * 128 + (((lane >> 3) & 1) * 16);

    float acc[128];
    #pragma unroll
    for (int i = 0; i < 128; i++) acc[i] = 0.f;

    loadStage(0, 0); asm volatile("cp.async.commit_group;" ::: "memory");
    loadStage(1, 1); asm volatile("cp.async.commit_group;" ::: "memory");

    for (int kt = 0; kt < KCH; kt++) {
        asm volatile("cp.async.wait_group 1;" ::: "memory");
        __syncthreads();
        int s = kt & 1;
        uint32_t sb = base + s * STG;
        #pragma unroll
        for (int ks = 0; ks < 4; ks++) {
            uint32_t ah[2][4];
            #pragma unroll
            for (int mt = 0; mt < 2; mt++)
                ldsm4(ah[mt], sb + OFF_AHI + SWZ(aOff[mt] + ks * 32));
            #pragma unroll
            for (int p = 0; p < 8; p++) {
                uint32_t bh[4];
                ldsm4(bh, sb + OFF_BHI + SWZ(bOff + p * 2048 + ks * 32));
                #pragma unroll
                for (int mt = 0; mt < 2; mt++) {
                    float* c0 = &acc[(mt * 16 + 2 * p) * 4];
                    float* c1 = &acc[(mt * 16 + 2 * p + 1) * 4];
                    mmah(c0, ah[mt], bh[0], bh[1]);
                    mmah(c1, ah[mt], bh[2], bh[3]);
                }
            }
        }
        __syncthreads();
        if (kt + 2 < KCH) loadStage(s, kt + 2);
        asm volatile("cp.async.commit_group;" ::: "memory");
    }

    // ---- epilogue ----
    int rq = lane >> 2, cq = (lane & 3) * 2;
    #pragma unroll
    for (int mt = 0; mt < 2; mt++) {
        #pragma unroll
        for (int h = 0; h < 2; h++) {
            int r = rowBase + m0 + mt * 16 + rq + h * 8;
            if (r < rows) {
                if (G1) {
                    size_t ro = ((size_t)e * CAP + r) * HDIM + colBase + n0 + cq;
                    #pragma unroll
                    for (int nt = 0; nt < 16; nt++) {
                        float v0 = gelu_tanh(acc[(mt * 16 + nt) * 4 + h * 2]);
                        float v1 = gelu_tanh(acc[(mt * 16 + nt) * 4 + h * 2 + 1]);
                        *(uint32_t*)(g_h_hi + ro + nt * 8) = packh(v0, v1);
                    }
                } else {
                    int tok = g_tfs[e * CAP + r];
                    float gw = g_gw[tok];
                    float* dst = outp + (size_t)tok * MDIM + colBase + n0 + cq;
                    #pragma unroll
                    for (int nt = 0; nt < 16; nt++) {
                        float2 v;
                        v.x = acc[(mt * 16 + nt) * 4 + h * 2]     * gw;
                        v.y = acc[(mt * 16 + nt) * 4 + h * 2 + 1] * gw;
                        *(float2*)(dst + nt * 8) = v;
                    }
                }
            }
        }
    }
}

// ----------------- launch ---------------------------------------------------
extern "C" void kernel_launch(void* const* d_in, const int* in_sizes, int n_in,
                              void* d_out, int out_size) {
    const float* x  = (const float*)d_in[0];
    const float* Wg = (const float*)d_in[1];
    const float* W1 = (const float*)d_in[2];
    const float* W2 = (const float*)d_in[3];
    float* out = (float*)d_out;

    cudaFuncSetAttribute(hgemm<true>,  cudaFuncAttributeMaxDynamicSharedMemorySize, SMEM_BYTES);
    cudaFuncSetAttribute(hgemm<false>, cudaFuncAttributeMaxDynamicSharedMemorySize, SMEM_BYTES);

    gate_kernel<<<S_TOK, 256>>>(x, Wg);
    route_kernel<<<1, 32>>>();
    split_x<<<(S_TOK * MDIM / 4) / 256, 256>>>((const float4*)x);
    transpose_split<true ><<<dim3(HDIM / 32, MDIM / 32, EEXP), dim3(32, 8)>>>(W1);
    transpose_split<false><<<dim3(MDIM / 32, HDIM / 32, EEXP), dim3(32, 8)>>>(W2);
    cudaMemsetAsync(d_out, 0, (size_t)S_TOK * MDIM * sizeof(float));
    hgemm<true ><<<dim3(HDIM / BN, CAP / BM, EEXP), 256, SMEM_BYTES>>>(nullptr);
    hgemm<false><<<dim3(MDIM / BN, CAP / BM, EEXP), 256, SMEM_BYTES>>>(out);
}

// round 7
// speedup vs baseline: 6.3337x; 1.1338x over previous
#include <cuda_runtime.h>
#include <cuda_fp16.h>
#include <cstdint>

#define S_TOK 8192
#define MDIM  2048
#define EEXP  8
#define HDIM  8192
#define CAP   2048

// ----------------- static device scratch -----------------------------------
__device__ int   g_idx[S_TOK];
__device__ float g_gw[S_TOK];
__device__ int   g_tfs[EEXP * CAP];
__device__ int   g_rows[EEXP];
__device__ __align__(128) __half g_x_hi[(size_t)S_TOK * MDIM];
__device__ __align__(128) __half g_h_hi[(size_t)EEXP * CAP * HDIM];
__device__ __align__(128) __half g_w1t_hi[(size_t)EEXP * HDIM * MDIM];
__device__ __align__(128) __half g_w2t_hi[(size_t)EEXP * MDIM * HDIM];

// ----------------- small helpers -------------------------------------------
__device__ __forceinline__ uint32_t smem_u32(const void* p) {
    uint32_t a;
    asm("{ .reg .u64 t; cvta.to.shared.u64 t, %1; cvt.u32.u64 %0, t; }" : "=r"(a) : "l"(p));
    return a;
}
__device__ __forceinline__ uint32_t SWZ(uint32_t o) { return o ^ ((o >> 3) & 0x70u); }

__device__ __forceinline__ uint32_t packh(float f0, float f1) {
    uint32_t r;
    asm("cvt.rn.f16x2.f32 %0, %1, %2;" : "=r"(r) : "f"(f1), "f"(f0));
    return r;
}
__device__ __forceinline__ void cpa(uint32_t d, const void* s) {
    asm volatile("cp.async.cg.shared.global [%0], [%1], 16;" :: "r"(d), "l"(s) : "memory");
}
__device__ __forceinline__ void ldsm4(uint32_t* r, uint32_t a) {
    asm volatile("ldmatrix.sync.aligned.m8n8.x4.shared.b16 {%0,%1,%2,%3}, [%4];"
                 : "=r"(r[0]), "=r"(r[1]), "=r"(r[2]), "=r"(r[3]) : "r"(a));
}
__device__ __forceinline__ void mmah(float* c, const uint32_t* a, uint32_t b0, uint32_t b1) {
    asm volatile("mma.sync.aligned.m16n8k16.row.col.f32.f16.f16.f32 "
                 "{%0,%1,%2,%3}, {%4,%5,%6,%7}, {%8,%9}, {%0,%1,%2,%3};"
                 : "+f"(c[0]), "+f"(c[1]), "+f"(c[2]), "+f"(c[3])
                 : "r"(a[0]), "r"(a[1]), "r"(a[2]), "r"(a[3]), "r"(b0), "r"(b1));
}
__device__ __forceinline__ float gelu_tanh(float v) {
    float t = tanhf(0.7978845608028654f * (v + 0.044715f * v * v * v));
    return 0.5f * v * (1.f + t);
}

// ----------------- gate ----------------------------------------------------
__global__ void gate_kernel(const float* __restrict__ x, const float* __restrict__ Wg) {
    int s = blockIdx.x;
    int w = threadIdx.x >> 5, lane = threadIdx.x & 31;
    const float* xr = x + (size_t)s * MDIM;
    float sum = 0.f;
    for (int m = lane; m < MDIM; m += 32)
        sum += xr[m] * Wg[m * EEXP + w];
    #pragma unroll
    for (int o = 16; o; o >>= 1) sum += __shfl_xor_sync(0xffffffffu, sum, o);
    __shared__ float lg[EEXP];
    if (lane == 0) lg[w] = sum;
    __syncthreads();
    if (threadIdx.x == 0) {
        float mx = lg[0]; int mi = 0;
        #pragma unroll
        for (int e = 1; e < EEXP; e++) if (lg[e] > mx) { mx = lg[e]; mi = e; }
        float se = 0.f;
        #pragma unroll
        for (int e = 0; e < EEXP; e++) se += expf(lg[e] - mx);
        g_idx[s] = mi;
        g_gw[s]  = 1.f / se;
    }
}

// ----------------- routing -------------------------------------------------
__global__ void route_kernel() {
    int lane = threadIdx.x;
    int cnt = 0;
    for (int s0 = 0; s0 < S_TOK; s0 += 32) {
        int s  = s0 + lane;
        int id = g_idx[s];
        int pos = 0;
        #pragma unroll
        for (int e = 0; e < EEXP; e++) {
            unsigned b = __ballot_sync(0xffffffffu, id == e);
            int base   = __shfl_sync(0xffffffffu, cnt, e);
            if (id == e)   pos = base + __popc(b & ((1u << lane) - 1u));
            if (lane == e) cnt += __popc(b);
        }
        if (pos < CAP) g_tfs[id * CAP + pos] = s;
        else           g_gw[s] = 0.f;
    }
    if (lane < EEXP) g_rows[lane] = min(cnt, CAP);
}

// ----------------- x convert to fp16 ----------------------------------------
__global__ void split_x(const float4* __restrict__ x) {
    size_t i = (size_t)blockIdx.x * 256 + threadIdx.x;   // S*M/4 total
    float4 v = x[i];
    ((uint2*)g_x_hi)[i] = make_uint2(packh(v.x, v.y), packh(v.z, v.w));
}

// ----------------- weight transpose (fp16) ----------------------------------
template<bool W1SEL>
__global__ void transpose_split(const float* __restrict__ src) {
    constexpr int R  = W1SEL ? MDIM : HDIM;   // src rows (= out cols = K)
    constexpr int Cc = W1SEL ? HDIM : MDIM;   // src cols (= out rows = N)
    __half* dhi = W1SEL ? g_w1t_hi : g_w2t_hi;
    __shared__ float t[32][33];
    int e = blockIdx.z;
    const float* s = src + (size_t)e * R * Cc;
    size_t ob = (size_t)e * R * Cc;
    int c0 = blockIdx.x * 32, r0 = blockIdx.y * 32;
    int tx = threadIdx.x, ty = threadIdx.y;
    #pragma unroll
    for (int k = 0; k < 4; k++)
        t[ty + 8 * k][tx] = s[(size_t)(r0 + ty + 8 * k) * Cc + c0 + tx];
    __syncthreads();
    #pragma unroll
    for (int k = 0; k < 4; k++) {
        float v = t[tx][ty + 8 * k];
        int orow = c0 + ty + 8 * k, ocol = r0 + tx;
        dhi[ob + (size_t)orow * R + ocol] = __float2half_rn(v);
    }
}

// ----------------- HMMA fp16 GEMM (BM=BN=128, 3 stages, 2 CTA/SM) -----------
#define BM 128
#define BN 128
#define BK 64
#define OFF_AHI 0
#define OFF_BHI 16384
#define STG 32768
#define SMEM_BYTES (3 * STG + 1024)

template<bool G1>
__global__ __launch_bounds__(256, 2)
void hgemm(float* __restrict__ outp) {
    constexpr int KD  = G1 ? MDIM : HDIM;
    constexpr int NT  = G1 ? HDIM : MDIM;
    constexpr int KCH = KD / BK;

    int e = blockIdx.z;
    int rows = g_rows[e];
    int rowBase = blockIdx.y * BM;
    if (rowBase >= rows) return;
    int colBase = blockIdx.x * BN;

    extern __shared__ char dsm[];
    uint32_t base = (smem_u32(dsm) + 1023u) & ~1023u;

    int t = threadIdx.x;

    // ---- loader setup: thread t loads 64B half of row (t>>1) ----
    int lr = t >> 1, half = t & 1;
    const __half* aHi;
    if (G1) {
        int rr = rowBase + lr;
        if (rr >= rows) rr = rows - 1;
        int tok = g_tfs[e * CAP + rr];
        aHi = g_x_hi + (size_t)tok * MDIM + half * 32;
    } else {
        aHi = g_h_hi + ((size_t)e * CAP + rowBase + lr) * HDIM + half * 32;
    }
    size_t bo0 = ((size_t)e * NT + colBase + lr) * KD + half * 32;
    const __half* bHi = G1 ? g_w1t_hi : g_w2t_hi;

    uint32_t d0[4];
    #pragma unroll
    for (int i = 0; i < 4; i++)
        d0[i] = SWZ(lr * 128 + (half * 4 + i) * 16);

    auto loadStage = [&](int s, int kt) {
        uint32_t sb = base + s * STG;
        int ko = kt * BK;
        #pragma unroll
        for (int i = 0; i < 4; i++) {
            cpa(sb + OFF_AHI + d0[i], aHi + ko + i * 8);
            cpa(sb + OFF_BHI + d0[i], bHi + bo0 + ko + i * 8);
        }
    };

    // ---- compute setup: 8 warps as 4(m) x 2(n); warp tile 32 x 64 ----
    int wid = t >> 5, lane = t & 31;
    int m0 = (wid >> 1) * 32, n0 = (wid & 1) * 64;
    uint32_t aOff[2];
    #pragma unroll
    for (int mt = 0; mt < 2; mt++)
        aOff[mt] = (m0 + mt * 16 + (lane & 15)) * 128 + ((lane >> 4) * 16);
    uint32_t bOff = (n0 + (lane & 7) + ((lane >> 4) << 3)) * 128 + (((lane >> 3) & 1) * 16);

    float acc[64];
    #pragma unroll
    for (int i = 0; i < 64; i++) acc[i] = 0.f;

    loadStage(0, 0); asm volatile("cp.async.commit_group;" ::: "memory");
    loadStage(1, 1); asm volatile("cp.async.commit_group;" ::: "memory");

    int sIdx = 0;
    for (int kt = 0; kt < KCH; kt++) {
        asm volatile("cp.async.wait_group 1;" ::: "memory");
        __syncthreads();
        // load next+1 stage (its buffer was consumed at kt-1; barrier above protects it)
        if (kt + 2 < KCH) {
            int ns = sIdx + 2; if (ns >= 3) ns -= 3;
            loadStage(ns, kt + 2);
        }
        asm volatile("cp.async.commit_group;" ::: "memory");

        uint32_t sb = base + sIdx * STG;
        #pragma unroll
        for (int ks = 0; ks < 4; ks++) {
            uint32_t ah[2][4];
            #pragma unroll
            for (int mt = 0; mt < 2; mt++)
                ldsm4(ah[mt], sb + OFF_AHI + SWZ(aOff[mt] + ks * 32));
            #pragma unroll
            for (int p = 0; p < 4; p++) {
                uint32_t bh[4];
                ldsm4(bh, sb + OFF_BHI + SWZ(bOff + p * 2048 + ks * 32));
                #pragma unroll
                for (int mt = 0; mt < 2; mt++) {
                    float* c0 = &acc[(mt * 8 + 2 * p) * 4];
                    float* c1 = &acc[(mt * 8 + 2 * p + 1) * 4];
                    mmah(c0, ah[mt], bh[0], bh[1]);
                    mmah(c1, ah[mt], bh[2], bh[3]);
                }
            }
        }
        if (++sIdx == 3) sIdx = 0;
    }

    // ---- epilogue ----
    int rq = lane >> 2, cq = (lane & 3) * 2;
    #pragma unroll
    for (int mt = 0; mt < 2; mt++) {
        #pragma unroll
        for (int h = 0; h < 2; h++) {
            int r = rowBase + m0 + mt * 16 + rq + h * 8;
            if (r < rows) {
                if (G1) {
                    size_t ro = ((size_t)e * CAP + r) * HDIM + colBase + n0 + cq;
                    #pragma unroll
                    for (int nt = 0; nt < 8; nt++) {
                        float v0 = gelu_tanh(acc[(mt * 8 + nt) * 4 + h * 2]);
                        float v1 = gelu_tanh(acc[(mt * 8 + nt) * 4 + h * 2 + 1]);
                        *(uint32_t*)(g_h_hi + ro + nt * 8) = packh(v0, v1);
                    }
                } else {
                    int tok = g_tfs[e * CAP + r];
                    float gw = g_gw[tok];
                    float* dst = outp + (size_t)tok * MDIM + colBase + n0 + cq;
                    #pragma unroll
                    for (int nt = 0; nt < 8; nt++) {
                        float2 v;
                        v.x = acc[(mt * 8 + nt) * 4 + h * 2]     * gw;
                        v.y = acc[(mt * 8 + nt) * 4 + h * 2 + 1] * gw;
                        *(float2*)(dst + nt * 8) = v;
                    }
                }
            }
        }
    }
}

// ----------------- launch ---------------------------------------------------
extern "C" void kernel_launch(void* const* d_in, const int* in_sizes, int n_in,
                              void* d_out, int out_size) {
    const float* x  = (const float*)d_in[0];
    const float* Wg = (const float*)d_in[1];
    const float* W1 = (const float*)d_in[2];
    const float* W2 = (const float*)d_in[3];
    float* out = (float*)d_out;

    cudaFuncSetAttribute(hgemm<true>,  cudaFuncAttributeMaxDynamicSharedMemorySize, SMEM_BYTES);
    cudaFuncSetAttribute(hgemm<false>, cudaFuncAttributeMaxDynamicSharedMemorySize, SMEM_BYTES);

    gate_kernel<<<S_TOK, 256>>>(x, Wg);
    route_kernel<<<1, 32>>>();
    split_x<<<(S_TOK * MDIM / 4) / 256, 256>>>((const float4*)x);
    transpose_split<true ><<<dim3(HDIM / 32, MDIM / 32, EEXP), dim3(32, 8)>>>(W1);
    transpose_split<false><<<dim3(MDIM / 32, HDIM / 32, EEXP), dim3(32, 8)>>>(W2);
    cudaMemsetAsync(d_out, 0, (size_t)S_TOK * MDIM * sizeof(float));
    hgemm<true ><<<dim3(HDIM / BN, CAP / BM, EEXP), 256, SMEM_BYTES>>>(nullptr);
    hgemm<false><<<dim3(MDIM / BN, CAP / BM, EEXP), 256, SMEM_BYTES>>>(out);
}